// round 5
// baseline (speedup 1.0000x reference)
#include <cuda_runtime.h>

#define N_AG 512
#define T_STEPS 12
#define NB 128
#define NT 512
typedef unsigned long long ull;

// ------------------------- cross-block scratch -------------------------
__device__ float2 g_B2buf[2][32 * N_AG];       // [buf][dd*512 + j] = (B[j][2dd], B[j][2dd+1])
__device__ unsigned g_cnt[T_STEPS];
__device__ volatile unsigned g_flag[T_STEPS];
__device__ unsigned g_depart;

__device__ __forceinline__ float sigf(float x) { return 1.f / (1.f + __expf(-x)); }

__device__ __forceinline__ ull add2(ull a, ull b) {
    ull r; asm("add.rn.f32x2 %0, %1, %2;" : "=l"(r) : "l"(a), "l"(b)); return r;
}
__device__ __forceinline__ void fma2(ull& d, ull a, ull b) {
    asm("fma.rn.f32x2 %0, %1, %2, %0;" : "+l"(d) : "l"(a), "l"(b));
}
__device__ __forceinline__ void unpack2(ull v, float& lo, float& hi) {
    asm("mov.b64 {%0, %1}, %2;" : "=f"(lo), "=f"(hi) : "l"(v));
}
__device__ __forceinline__ ull pack2f(float lo, float hi) {
    ull r; asm("mov.b64 %0, {%1, %2};" : "=l"(r) : "f"(lo), "f"(hi)); return r;
}

__global__ __launch_bounds__(NT, 1) void k_fused(
    const float* __restrict__ p, const float* __restrict__ c, const float* __restrict__ z,
    const float* __restrict__ obs, const float* __restrict__ eps, const float* __restrict__ c0,
    const int* __restrict__ nei,
    const float* __restrict__ W_in, const float* __restrict__ b_in,
    const float* __restrict__ W_ih, const float* __restrict__ W_hh,
    const float* __restrict__ b_ih, const float* __restrict__ b_hh,
    const float* __restrict__ W_m, const float* __restrict__ b_m,
    const float* __restrict__ W_v, const float* __restrict__ b_v,
    const float* __restrict__ W_zh, const float* __restrict__ b_zh,
    const float* __restrict__ W_se, const float* __restrict__ b_se,
    const float* __restrict__ W1, const float* __restrict__ b1,
    const float* __restrict__ W2, const float* __restrict__ b2,
    float* __restrict__ out)
{
    __shared__ ull    w2d[32][2][8];   // [dd][r][k] = dup(W2[2dd+r][k]) as (w,w) packed
    __shared__ ull    Apk[4][32];      // packed (A[i][2dd], A[i][2dd+1]) per agent
    __shared__ float  sh_Mse0[64];
    __shared__ float  sh_Mse1[64];
    __shared__ float  sh_b1[64];
    __shared__ float  sh_b2[8];
    __shared__ float  sh_h[4][8], sh_cl[4][8], sh_ctx[4][8];
    __shared__ float2 sh_pos[4], sh_prev[4];
    __shared__ float  red[16][8];

    const int tid  = threadIdx.x;
    const int warp = tid >> 5;
    const int lane = tid & 31;
    const int blk  = blockIdx.x;

    // ---------------- preload constants ----------------
    {
        // w2d: 512 entries, one per thread
        int dd = tid >> 4, r = (tid >> 3) & 1, k = tid & 7;
        float w = W2[(2 * dd + r) * 8 + k];
        w2d[dd][r][k] = pack2f(w, w);
    }
    if (tid < 64) {
        int d = tid;
        float m0 = 0.f, m1 = 0.f, bb = b1[d];
        for (int u = 0; u < 32; u++) {
            float w = W1[u * 64 + d];
            m0 += W_se[u] * w;
            m1 += W_se[32 + u] * w;
            bb += b_se[u] * w;
        }
        sh_Mse0[d] = m0; sh_Mse1[d] = m1; sh_b1[d] = bb;
    } else if (tid < 72) {
        sh_b2[tid - 64] = b2[tid - 64];
    }

    // ---------------- init per-agent state (warps 0..3) ----------------
    if (warp < 4) {
        int i = blk * 4 + warp;
        if (lane < 8) {
            float z0 = z[2 * i], z1 = z[2 * i + 1];
            sh_h[warp][lane]   = z0 * W_zh[lane] + z1 * W_zh[8 + lane] + b_zh[lane];
            sh_cl[warp][lane]  = c0[i * 8 + lane];
            sh_ctx[warp][lane] = 0.f;
        }
        if (lane == 0) {
            sh_pos[warp]  = make_float2(obs[(7 * N_AG + i) * 2], obs[(7 * N_AG + i) * 2 + 1]);
            sh_prev[warp] = make_float2(p[2 * i], p[2 * i + 1]);
        }
    }
    __syncthreads();

    for (int t = 0; t <= T_STEPS; t++) {
        // ================= step phase (warps 0..3, one agent each) =================
        if (warp < 4) {
            int a = warp;
            int i = blk * 4 + a;

            if (t >= 1 && lane < 8) {
                float v = fmaxf(fmaxf(red[a * 4 + 0][lane], red[a * 4 + 1][lane]),
                                fmaxf(red[a * 4 + 2][lane], red[a * 4 + 3][lane]));
                sh_ctx[a][lane] = v;
            }
            __syncwarp();

            float h[8], ctx[8];
#pragma unroll
            for (int u = 0; u < 8; u++) { h[u] = sh_h[a][u]; ctx[u] = sh_ctx[a][u]; }
            float cl8 = sh_cl[a][lane & 7];

            float pos0, pos1, pv0, pv1;
            if (t > 0) {
                int tc = t - 1;
                float mu[2], lv[2];
#pragma unroll
                for (int m = 0; m < 2; m++) {
                    float s  = b_m[m];
                    float s2 = b_v[m];
#pragma unroll
                    for (int u = 0; u < 4; u++) {
                        s  += h[u]     * W_m[u * 2 + m];
                        s2 += h[4 + u] * W_v[u * 2 + m];
                    }
#pragma unroll
                    for (int k = 0; k < 8; k++) {
                        s  += ctx[k] * W_m[(4 + k) * 2 + m];
                        s2 += ctx[k] * W_v[(4 + k) * 2 + m];
                    }
                    mu[m] = s; lv[m] = s2;
                }
                float e0 = eps[(tc * N_AG + i) * 2];
                float e1 = eps[(tc * N_AG + i) * 2 + 1];
                float p0 = mu[0] + e0 * expf(0.5f * lv[0]);
                float p1 = mu[1] + e1 * expf(0.5f * lv[1]);
                pv0 = p0; pv1 = p1;
                pos0 = sh_pos[a].x + p0;
                pos1 = sh_pos[a].y + p1;
                if (lane == 0) {
                    out[tc * 1024 + 2 * i]             = p0;
                    out[tc * 1024 + 2 * i + 1]         = p1;
                    out[12288 + tc * 1024 + 2 * i]     = mu[0];
                    out[12288 + tc * 1024 + 2 * i + 1] = mu[1];
                    out[24576 + tc * 1024 + 2 * i]     = lv[0];
                    out[24576 + tc * 1024 + 2 * i + 1] = lv[1];
                    sh_prev[a] = make_float2(pv0, pv1);
                    sh_pos[a]  = make_float2(pos0, pos1);
                }
            } else {
                pv0 = sh_prev[a].x; pv1 = sh_prev[a].y;
                pos0 = sh_pos[a].x; pos1 = sh_pos[a].y;
            }

            if (t < T_STEPS) {
                float x[20];
#pragma unroll
                for (int u = 0; u < 8; u++) x[u] = ctx[u];
                x[8] = pv0; x[9] = pv1;
#pragma unroll
                for (int u = 0; u < 8; u++) x[10 + u] = c[i * 8 + u];
                x[18] = z[2 * i]; x[19] = z[2 * i + 1];

                float xr = 0.f;
                if (lane < 16) {
                    float s = b_in[lane];
#pragma unroll
                    for (int v = 0; v < 20; v++) s += x[v] * W_in[v * 16 + lane];
                    xr = fmaxf(s, 0.f);
                }

                float g = b_ih[lane] + b_hh[lane];
#pragma unroll
                for (int u = 0; u < 16; u++) {
                    float xu = __shfl_sync(0xffffffffu, xr, u);
                    g += xu * W_ih[u * 32 + lane];
                }
#pragma unroll
                for (int u = 0; u < 8; u++) g += h[u] * W_hh[u * 32 + lane];

                int u8 = lane & 7;
                float gi = __shfl_sync(0xffffffffu, g, u8);
                float gf = __shfl_sync(0xffffffffu, g, u8 + 8);
                float gg = __shfl_sync(0xffffffffu, g, u8 + 16);
                float go = __shfl_sync(0xffffffffu, g, u8 + 24);
                float cln = sigf(gf) * cl8 + sigf(gi) * tanhf(gg);
                float hn  = sigf(go) * tanhf(cln);
                if (lane < 8) {
                    sh_cl[a][lane] = cln;
                    sh_h[a][lane]  = hn;
                }
                float hw[8];
#pragma unroll
                for (int u = 0; u < 8; u++) hw[u] = __shfl_sync(0xffffffffu, hn, u);

                // A/B precompute: lane owns d-pair (2l, 2l+1)
                int d = 2 * lane;
                float m0x = sh_Mse0[d],  m0y = sh_Mse0[d + 1];
                float m1x = sh_Mse1[d],  m1y = sh_Mse1[d + 1];
                float bx = pos0 * m0x + pos1 * m1x;
                float by = pos0 * m0y + pos1 * m1y;
                float Ax = sh_b1[d] + bx,     Ay = sh_b1[d + 1] + by;
                float Bx = -bx,               By = -by;
#pragma unroll
                for (int u = 0; u < 8; u++) {
                    float2 wA = *(const float2*)(W1 + (40 + u) * 64 + d);
                    float2 wB = *(const float2*)(W1 + (32 + u) * 64 + d);
                    Ax = fmaf(hw[u], wA.x, Ax); Ay = fmaf(hw[u], wA.y, Ay);
                    Bx = fmaf(hw[u], wB.x, Bx); By = fmaf(hw[u], wB.y, By);
                }
                Apk[a][lane] = pack2f(Ax, Ay);
                g_B2buf[t & 1][lane * N_AG + i] = make_float2(Bx, By);
            }
        }
        if (t == T_STEPS) break;
        __syncthreads();

        // ================= grid barrier t =================
        if (tid == 0) {
            __threadfence();
            unsigned v = atomicAdd(&g_cnt[t], 1u);
            if (v == NB - 1) {
                if (t > 0) { g_cnt[t - 1] = 0; g_flag[t - 1] = 0; }
                g_flag[t] = 1;
                __threadfence();
            } else {
                while (g_flag[t] == 0) { }
            }
            __threadfence();
        }
        __syncthreads();

        // ================= pool phase (all 16 warps), packed f32x2 =================
        {
            int a = warp >> 2;
            int i = blk * 4 + a;
            int t128 = (warp & 3) * 32 + lane;
            const ulonglong2* U2 = (const ulonglong2*)g_B2buf[t & 1];
            const int4 nm = *(const int4*)(nei + ((long)t * N_AG + i) * N_AG + 4 * t128);

            // acc[jj][k]: lo = dot for j=4*t128+2jj, hi = j=4*t128+2jj+1
            ull acc[2][8];
#pragma unroll
            for (int jj = 0; jj < 2; jj++)
#pragma unroll
                for (int k = 0; k < 8; k++) acc[jj][k] = 0ULL;

#pragma unroll 4
            for (int dd = 0; dd < 32; dd++) {
                ull avp = Apk[a][dd];
                ulonglong2 q0 = U2[dd * 256 + 2 * t128];
                ulonglong2 q1 = U2[dd * 256 + 2 * t128 + 1];
                ull s0 = add2(avp, q0.x);
                ull s1 = add2(avp, q0.y);
                ull s2 = add2(avp, q1.x);
                ull s3 = add2(avp, q1.y);
                float t0x, t0y, t1x, t1y, t2x, t2y, t3x, t3y;
                unpack2(s0, t0x, t0y); unpack2(s1, t1x, t1y);
                unpack2(s2, t2x, t2y); unpack2(s3, t3x, t3y);
                t0x = fmaxf(t0x, 0.f); t0y = fmaxf(t0y, 0.f);
                t1x = fmaxf(t1x, 0.f); t1y = fmaxf(t1y, 0.f);
                t2x = fmaxf(t2x, 0.f); t2y = fmaxf(t2y, 0.f);
                t3x = fmaxf(t3x, 0.f); t3y = fmaxf(t3y, 0.f);
                ull px0 = pack2f(t0x, t1x);   // x comps, j-pair 0
                ull py0 = pack2f(t0y, t1y);
                ull px1 = pack2f(t2x, t3x);   // x comps, j-pair 1
                ull py1 = pack2f(t2y, t3y);
                const ull* wa = w2d[dd][0];
                const ull* wb = w2d[dd][1];
#pragma unroll
                for (int k = 0; k < 8; k++) {
                    ull wak = wa[k], wbk = wb[k];
                    fma2(acc[0][k], px0, wak);
                    fma2(acc[0][k], py0, wbk);
                    fma2(acc[1][k], px1, wak);
                    fma2(acc[1][k], py1, wbk);
                }
            }

            float m[8];
            int n0 = nm.x, n1 = nm.y, n2 = nm.z, n3 = nm.w;
#pragma unroll
            for (int k = 0; k < 8; k++) {
                float bk = sh_b2[k];
                float v0, v1, v2, v3;
                unpack2(acc[0][k], v0, v1);
                unpack2(acc[1][k], v2, v3);
                float v = 0.f;
                float s0 = fmaxf(v0 + bk, 0.f);
                float s1 = fmaxf(v1 + bk, 0.f);
                float s2 = fmaxf(v2 + bk, 0.f);
                float s3 = fmaxf(v3 + bk, 0.f);
                if (n0 > 0) v = fmaxf(v, s0);
                if (n1 > 0) v = fmaxf(v, s1);
                if (n2 > 0) v = fmaxf(v, s2);
                if (n3 > 0) v = fmaxf(v, s3);
                v = fmaxf(v, __shfl_xor_sync(0xffffffffu, v, 16));
                v = fmaxf(v, __shfl_xor_sync(0xffffffffu, v, 8));
                v = fmaxf(v, __shfl_xor_sync(0xffffffffu, v, 4));
                v = fmaxf(v, __shfl_xor_sync(0xffffffffu, v, 2));
                v = fmaxf(v, __shfl_xor_sync(0xffffffffu, v, 1));
                m[k] = v;
            }
            if (lane < 8) red[warp][lane] = m[lane];
        }
        __syncthreads();
    }

    // ---------------- replay-safe cleanup of last barrier ----------------
    if (tid == 0) {
        __threadfence();
        unsigned d = atomicAdd(&g_depart, 1u);
        if (d == NB - 1) {
            g_cnt[T_STEPS - 1] = 0;
            g_flag[T_STEPS - 1] = 0;
            g_depart = 0;
            __threadfence();
        }
    }
}

// ------------------------- launch -------------------------
extern "C" void kernel_launch(void* const* d_in, const int* in_sizes, int n_in,
                              void* d_out, int out_size)
{
    const float* p    = (const float*)d_in[0];
    const float* c    = (const float*)d_in[1];
    const float* z    = (const float*)d_in[2];
    const float* obs  = (const float*)d_in[3];
    const float* eps  = (const float*)d_in[4];
    const float* c0   = (const float*)d_in[5];
    const int*   nei  = (const int*)d_in[6];
    const float* W_in = (const float*)d_in[8];
    const float* b_in = (const float*)d_in[9];
    const float* W_ih = (const float*)d_in[10];
    const float* W_hh = (const float*)d_in[11];
    const float* b_ih = (const float*)d_in[12];
    const float* b_hh = (const float*)d_in[13];
    const float* W_m  = (const float*)d_in[14];
    const float* b_m  = (const float*)d_in[15];
    const float* W_v  = (const float*)d_in[16];
    const float* b_v  = (const float*)d_in[17];
    const float* W_zh = (const float*)d_in[18];
    const float* b_zh = (const float*)d_in[19];
    const float* W_se = (const float*)d_in[20];
    const float* b_se = (const float*)d_in[21];
    const float* W1   = (const float*)d_in[22];
    const float* b1   = (const float*)d_in[23];
    const float* W2   = (const float*)d_in[24];
    const float* b2   = (const float*)d_in[25];
    float* out = (float*)d_out;

    k_fused<<<NB, NT>>>(p, c, z, obs, eps, c0, nei,
                        W_in, b_in, W_ih, W_hh, b_ih, b_hh,
                        W_m, b_m, W_v, b_v, W_zh, b_zh,
                        W_se, b_se, W1, b1, W2, b2, out);
}

// round 6
// speedup vs baseline: 1.0004x; 1.0004x over previous
#include <cuda_runtime.h>

#define N_AG 512
#define T_STEPS 12
#define NB 128
#define NT 512
typedef unsigned long long ull;

// ------------------------- cross-block scratch -------------------------
__device__ float2 g_B2buf[2][32 * N_AG];       // [buf][dd*512 + j] = (B[j][2dd], B[j][2dd+1])
__device__ unsigned g_cnt[T_STEPS];
__device__ volatile unsigned g_flag[T_STEPS];
__device__ unsigned g_depart;

__device__ __forceinline__ float sigf(float x) { return 1.f / (1.f + __expf(-x)); }

__device__ __forceinline__ ull add2(ull a, ull b) {
    ull r; asm("add.rn.f32x2 %0, %1, %2;" : "=l"(r) : "l"(a), "l"(b)); return r;
}
__device__ __forceinline__ void fma2(ull& d, ull a, ull b) {
    asm("fma.rn.f32x2 %0, %1, %2, %0;" : "+l"(d) : "l"(a), "l"(b));
}
__device__ __forceinline__ void unpack2(ull v, float& lo, float& hi) {
    asm("mov.b64 {%0, %1}, %2;" : "=f"(lo), "=f"(hi) : "l"(v));
}
__device__ __forceinline__ ull pack2f(float lo, float hi) {
    ull r; asm("mov.b64 %0, {%1, %2};" : "=l"(r) : "f"(lo), "f"(hi)); return r;
}

__global__ __launch_bounds__(NT, 1) void k_fused(
    const float* __restrict__ p, const float* __restrict__ c, const float* __restrict__ z,
    const float* __restrict__ obs, const float* __restrict__ eps, const float* __restrict__ c0,
    const int* __restrict__ nei,
    const float* __restrict__ W_in, const float* __restrict__ b_in,
    const float* __restrict__ W_ih, const float* __restrict__ W_hh,
    const float* __restrict__ b_ih, const float* __restrict__ b_hh,
    const float* __restrict__ W_m, const float* __restrict__ b_m,
    const float* __restrict__ W_v, const float* __restrict__ b_v,
    const float* __restrict__ W_zh, const float* __restrict__ b_zh,
    const float* __restrict__ W_se, const float* __restrict__ b_se,
    const float* __restrict__ W1, const float* __restrict__ b1,
    const float* __restrict__ W2, const float* __restrict__ b2,
    float* __restrict__ out)
{
    __shared__ ull    w2d[32][2][8];   // [dd][r][k] = dup(W2[2dd+r][k]) as (w,w) packed
    __shared__ ull    Apk[4][32];      // packed (A[i][2dd], A[i][2dd+1]) per agent
    __shared__ float  sh_Mse0[64];
    __shared__ float  sh_Mse1[64];
    __shared__ float  sh_b1[64];
    __shared__ float  sh_b2[8];
    __shared__ float  sh_h[4][8], sh_cl[4][8], sh_ctx[4][8];
    __shared__ float2 sh_pos[4], sh_prev[4];
    __shared__ float  red[16][8];

    const int tid  = threadIdx.x;
    const int warp = tid >> 5;
    const int lane = tid & 31;
    const int blk  = blockIdx.x;

    // ---------------- preload constants ----------------
    {
        // w2d: 512 entries, one per thread
        int dd = tid >> 4, r = (tid >> 3) & 1, k = tid & 7;
        float w = W2[(2 * dd + r) * 8 + k];
        w2d[dd][r][k] = pack2f(w, w);
    }
    if (tid < 64) {
        int d = tid;
        float m0 = 0.f, m1 = 0.f, bb = b1[d];
        for (int u = 0; u < 32; u++) {
            float w = W1[u * 64 + d];
            m0 += W_se[u] * w;
            m1 += W_se[32 + u] * w;
            bb += b_se[u] * w;
        }
        sh_Mse0[d] = m0; sh_Mse1[d] = m1; sh_b1[d] = bb;
    } else if (tid < 72) {
        sh_b2[tid - 64] = b2[tid - 64];
    }

    // ---------------- init per-agent state (warps 0..3) ----------------
    if (warp < 4) {
        int i = blk * 4 + warp;
        if (lane < 8) {
            float z0 = z[2 * i], z1 = z[2 * i + 1];
            sh_h[warp][lane]   = z0 * W_zh[lane] + z1 * W_zh[8 + lane] + b_zh[lane];
            sh_cl[warp][lane]  = c0[i * 8 + lane];
            sh_ctx[warp][lane] = 0.f;
        }
        if (lane == 0) {
            sh_pos[warp]  = make_float2(obs[(7 * N_AG + i) * 2], obs[(7 * N_AG + i) * 2 + 1]);
            sh_prev[warp] = make_float2(p[2 * i], p[2 * i + 1]);
        }
    }
    __syncthreads();

    for (int t = 0; t <= T_STEPS; t++) {
        // ================= step phase (warps 0..3, one agent each) =================
        if (warp < 4) {
            int a = warp;
            int i = blk * 4 + a;

            if (t >= 1 && lane < 8) {
                float v = fmaxf(fmaxf(red[a * 4 + 0][lane], red[a * 4 + 1][lane]),
                                fmaxf(red[a * 4 + 2][lane], red[a * 4 + 3][lane]));
                sh_ctx[a][lane] = v;
            }
            __syncwarp();

            float h[8], ctx[8];
#pragma unroll
            for (int u = 0; u < 8; u++) { h[u] = sh_h[a][u]; ctx[u] = sh_ctx[a][u]; }
            float cl8 = sh_cl[a][lane & 7];

            float pos0, pos1, pv0, pv1;
            if (t > 0) {
                int tc = t - 1;
                float mu[2], lv[2];
#pragma unroll
                for (int m = 0; m < 2; m++) {
                    float s  = b_m[m];
                    float s2 = b_v[m];
#pragma unroll
                    for (int u = 0; u < 4; u++) {
                        s  += h[u]     * W_m[u * 2 + m];
                        s2 += h[4 + u] * W_v[u * 2 + m];
                    }
#pragma unroll
                    for (int k = 0; k < 8; k++) {
                        s  += ctx[k] * W_m[(4 + k) * 2 + m];
                        s2 += ctx[k] * W_v[(4 + k) * 2 + m];
                    }
                    mu[m] = s; lv[m] = s2;
                }
                float e0 = eps[(tc * N_AG + i) * 2];
                float e1 = eps[(tc * N_AG + i) * 2 + 1];
                float p0 = mu[0] + e0 * expf(0.5f * lv[0]);
                float p1 = mu[1] + e1 * expf(0.5f * lv[1]);
                pv0 = p0; pv1 = p1;
                pos0 = sh_pos[a].x + p0;
                pos1 = sh_pos[a].y + p1;
                if (lane == 0) {
                    out[tc * 1024 + 2 * i]             = p0;
                    out[tc * 1024 + 2 * i + 1]         = p1;
                    out[12288 + tc * 1024 + 2 * i]     = mu[0];
                    out[12288 + tc * 1024 + 2 * i + 1] = mu[1];
                    out[24576 + tc * 1024 + 2 * i]     = lv[0];
                    out[24576 + tc * 1024 + 2 * i + 1] = lv[1];
                    sh_prev[a] = make_float2(pv0, pv1);
                    sh_pos[a]  = make_float2(pos0, pos1);
                }
            } else {
                pv0 = sh_prev[a].x; pv1 = sh_prev[a].y;
                pos0 = sh_pos[a].x; pos1 = sh_pos[a].y;
            }

            if (t < T_STEPS) {
                float x[20];
#pragma unroll
                for (int u = 0; u < 8; u++) x[u] = ctx[u];
                x[8] = pv0; x[9] = pv1;
#pragma unroll
                for (int u = 0; u < 8; u++) x[10 + u] = c[i * 8 + u];
                x[18] = z[2 * i]; x[19] = z[2 * i + 1];

                float xr = 0.f;
                if (lane < 16) {
                    float s = b_in[lane];
#pragma unroll
                    for (int v = 0; v < 20; v++) s += x[v] * W_in[v * 16 + lane];
                    xr = fmaxf(s, 0.f);
                }

                float g = b_ih[lane] + b_hh[lane];
#pragma unroll
                for (int u = 0; u < 16; u++) {
                    float xu = __shfl_sync(0xffffffffu, xr, u);
                    g += xu * W_ih[u * 32 + lane];
                }
#pragma unroll
                for (int u = 0; u < 8; u++) g += h[u] * W_hh[u * 32 + lane];

                int u8 = lane & 7;
                float gi = __shfl_sync(0xffffffffu, g, u8);
                float gf = __shfl_sync(0xffffffffu, g, u8 + 8);
                float gg = __shfl_sync(0xffffffffu, g, u8 + 16);
                float go = __shfl_sync(0xffffffffu, g, u8 + 24);
                float cln = sigf(gf) * cl8 + sigf(gi) * tanhf(gg);
                float hn  = sigf(go) * tanhf(cln);
                if (lane < 8) {
                    sh_cl[a][lane] = cln;
                    sh_h[a][lane]  = hn;
                }
                float hw[8];
#pragma unroll
                for (int u = 0; u < 8; u++) hw[u] = __shfl_sync(0xffffffffu, hn, u);

                // A/B precompute: lane owns d-pair (2l, 2l+1)
                int d = 2 * lane;
                float m0x = sh_Mse0[d],  m0y = sh_Mse0[d + 1];
                float m1x = sh_Mse1[d],  m1y = sh_Mse1[d + 1];
                float bx = pos0 * m0x + pos1 * m1x;
                float by = pos0 * m0y + pos1 * m1y;
                float Ax = sh_b1[d] + bx,     Ay = sh_b1[d + 1] + by;
                float Bx = -bx,               By = -by;
#pragma unroll
                for (int u = 0; u < 8; u++) {
                    float2 wA = *(const float2*)(W1 + (40 + u) * 64 + d);
                    float2 wB = *(const float2*)(W1 + (32 + u) * 64 + d);
                    Ax = fmaf(hw[u], wA.x, Ax); Ay = fmaf(hw[u], wA.y, Ay);
                    Bx = fmaf(hw[u], wB.x, Bx); By = fmaf(hw[u], wB.y, By);
                }
                Apk[a][lane] = pack2f(Ax, Ay);
                g_B2buf[t & 1][lane * N_AG + i] = make_float2(Bx, By);
            }
        }
        if (t == T_STEPS) break;
        __syncthreads();

        // ================= grid barrier t =================
        if (tid == 0) {
            __threadfence();
            unsigned v = atomicAdd(&g_cnt[t], 1u);
            if (v == NB - 1) {
                if (t > 0) { g_cnt[t - 1] = 0; g_flag[t - 1] = 0; }
                g_flag[t] = 1;
                __threadfence();
            } else {
                while (g_flag[t] == 0) { }
            }
            __threadfence();
        }
        __syncthreads();

        // ================= pool phase (all 16 warps), packed f32x2 =================
        {
            int a = warp >> 2;
            int i = blk * 4 + a;
            int t128 = (warp & 3) * 32 + lane;
            const ulonglong2* U2 = (const ulonglong2*)g_B2buf[t & 1];
            const int4 nm = *(const int4*)(nei + ((long)t * N_AG + i) * N_AG + 4 * t128);

            // acc[jj][k]: lo = dot for j=4*t128+2jj, hi = j=4*t128+2jj+1
            ull acc[2][8];
#pragma unroll
            for (int jj = 0; jj < 2; jj++)
#pragma unroll
                for (int k = 0; k < 8; k++) acc[jj][k] = 0ULL;

#pragma unroll 4
            for (int dd = 0; dd < 32; dd++) {
                ull avp = Apk[a][dd];
                ulonglong2 q0 = U2[dd * 256 + 2 * t128];
                ulonglong2 q1 = U2[dd * 256 + 2 * t128 + 1];
                ull s0 = add2(avp, q0.x);
                ull s1 = add2(avp, q0.y);
                ull s2 = add2(avp, q1.x);
                ull s3 = add2(avp, q1.y);
                float t0x, t0y, t1x, t1y, t2x, t2y, t3x, t3y;
                unpack2(s0, t0x, t0y); unpack2(s1, t1x, t1y);
                unpack2(s2, t2x, t2y); unpack2(s3, t3x, t3y);
                t0x = fmaxf(t0x, 0.f); t0y = fmaxf(t0y, 0.f);
                t1x = fmaxf(t1x, 0.f); t1y = fmaxf(t1y, 0.f);
                t2x = fmaxf(t2x, 0.f); t2y = fmaxf(t2y, 0.f);
                t3x = fmaxf(t3x, 0.f); t3y = fmaxf(t3y, 0.f);
                ull px0 = pack2f(t0x, t1x);   // x comps, j-pair 0
                ull py0 = pack2f(t0y, t1y);
                ull px1 = pack2f(t2x, t3x);   // x comps, j-pair 1
                ull py1 = pack2f(t2y, t3y);
                const ull* wa = w2d[dd][0];
                const ull* wb = w2d[dd][1];
#pragma unroll
                for (int k = 0; k < 8; k++) {
                    ull wak = wa[k], wbk = wb[k];
                    fma2(acc[0][k], px0, wak);
                    fma2(acc[0][k], py0, wbk);
                    fma2(acc[1][k], px1, wak);
                    fma2(acc[1][k], py1, wbk);
                }
            }

            float m[8];
            int n0 = nm.x, n1 = nm.y, n2 = nm.z, n3 = nm.w;
#pragma unroll
            for (int k = 0; k < 8; k++) {
                float bk = sh_b2[k];
                float v0, v1, v2, v3;
                unpack2(acc[0][k], v0, v1);
                unpack2(acc[1][k], v2, v3);
                float v = 0.f;
                float s0 = fmaxf(v0 + bk, 0.f);
                float s1 = fmaxf(v1 + bk, 0.f);
                float s2 = fmaxf(v2 + bk, 0.f);
                float s3 = fmaxf(v3 + bk, 0.f);
                if (n0 > 0) v = fmaxf(v, s0);
                if (n1 > 0) v = fmaxf(v, s1);
                if (n2 > 0) v = fmaxf(v, s2);
                if (n3 > 0) v = fmaxf(v, s3);
                v = fmaxf(v, __shfl_xor_sync(0xffffffffu, v, 16));
                v = fmaxf(v, __shfl_xor_sync(0xffffffffu, v, 8));
                v = fmaxf(v, __shfl_xor_sync(0xffffffffu, v, 4));
                v = fmaxf(v, __shfl_xor_sync(0xffffffffu, v, 2));
                v = fmaxf(v, __shfl_xor_sync(0xffffffffu, v, 1));
                m[k] = v;
            }
            if (lane < 8) red[warp][lane] = m[lane];
        }
        __syncthreads();
    }

    // ---------------- replay-safe cleanup of last barrier ----------------
    if (tid == 0) {
        __threadfence();
        unsigned d = atomicAdd(&g_depart, 1u);
        if (d == NB - 1) {
            g_cnt[T_STEPS - 1] = 0;
            g_flag[T_STEPS - 1] = 0;
            g_depart = 0;
            __threadfence();
        }
    }
}

// ------------------------- launch -------------------------
extern "C" void kernel_launch(void* const* d_in, const int* in_sizes, int n_in,
                              void* d_out, int out_size)
{
    const float* p    = (const float*)d_in[0];
    const float* c    = (const float*)d_in[1];
    const float* z    = (const float*)d_in[2];
    const float* obs  = (const float*)d_in[3];
    const float* eps  = (const float*)d_in[4];
    const float* c0   = (const float*)d_in[5];
    const int*   nei  = (const int*)d_in[6];
    const float* W_in = (const float*)d_in[8];
    const float* b_in = (const float*)d_in[9];
    const float* W_ih = (const float*)d_in[10];
    const float* W_hh = (const float*)d_in[11];
    const float* b_ih = (const float*)d_in[12];
    const float* b_hh = (const float*)d_in[13];
    const float* W_m  = (const float*)d_in[14];
    const float* b_m  = (const float*)d_in[15];
    const float* W_v  = (const float*)d_in[16];
    const float* b_v  = (const float*)d_in[17];
    const float* W_zh = (const float*)d_in[18];
    const float* b_zh = (const float*)d_in[19];
    const float* W_se = (const float*)d_in[20];
    const float* b_se = (const float*)d_in[21];
    const float* W1   = (const float*)d_in[22];
    const float* b1   = (const float*)d_in[23];
    const float* W2   = (const float*)d_in[24];
    const float* b2   = (const float*)d_in[25];
    float* out = (float*)d_out;

    k_fused<<<NB, NT>>>(p, c, z, obs, eps, c0, nei,
                        W_in, b_in, W_ih, W_hh, b_ih, b_hh,
                        W_m, b_m, W_v, b_v, W_zh, b_zh,
                        W_se, b_se, W1, b1, W2, b2, out);
}